// round 15
// baseline (speedup 1.0000x reference)
#include <cuda_runtime.h>
#include <cuda_bf16.h>
#include <math.h>
#include <stdint.h>

// Problem constants
#define BB 4
#define TT 1024
#define LL 12
#define HH 12
#define DD 768
#define HD 64
#define DF 3072
#define BT 4096          // B*T
#define NV 50257

// -------------------- scratch (device globals; no allocations) --------------------
__device__ float g_x  [BT * DD];
__device__ float g_ln [BT * DD];
__device__ float g_qkv[BT * 3 * DD];
__device__ float g_o  [BT * DD];
__device__ float g_mlp[BT * DF];

// -------------------- packed f32x2 helpers (Blackwell FFMA2) --------------------
typedef unsigned long long u64t;
__device__ __forceinline__ u64t pk2(float lo, float hi) {
    u64t r; asm("mov.b64 %0, {%1, %2};" : "=l"(r) : "f"(lo), "f"(hi)); return r;
}
__device__ __forceinline__ void upk2(u64t v, float& lo, float& hi) {
    asm("mov.b64 {%0, %1}, %2;" : "=f"(lo), "=f"(hi) : "l"(v));
}
__device__ __forceinline__ u64t ffma2(u64t a, u64t b, u64t c) {
    u64t d; asm("fma.rn.f32x2 %0, %1, %2, %3;" : "=l"(d) : "l"(a), "l"(b), "l"(c)); return d;
}
__device__ __forceinline__ u64t fmul2(u64t a, u64t b) {
    u64t d; asm("mul.rn.f32x2 %0, %1, %2;" : "=l"(d) : "l"(a), "l"(b)); return d;
}

// -------------------- embedding --------------------
__global__ void embed_kernel(const int* __restrict__ idx,
                             const float* __restrict__ wte,
                             const float* __restrict__ wpe,
                             float* __restrict__ x) {
    int i = blockIdx.x * 256 + threadIdx.x;
    if (i >= BT * DD) return;
    int bt = i / DD, d = i - bt * DD;
    int t = bt & (TT - 1);
    x[i] = wte[(size_t)idx[bt] * DD + d] + wpe[t * DD + d];
}

// -------------------- layernorm --------------------
__global__ __launch_bounds__(256) void ln_kernel(const float* __restrict__ in,
                                                 const float* __restrict__ g,
                                                 const float* __restrict__ b,
                                                 float* __restrict__ out) {
    int row = blockIdx.x;
    const float* x = in + (size_t)row * DD;
    float* y = out + (size_t)row * DD;
    int tid = threadIdx.x;
    float v[3];
    float s = 0.f, s2 = 0.f;
#pragma unroll
    for (int i = 0; i < 3; i++) {
        v[i] = x[tid + i * 256];
        s += v[i]; s2 += v[i] * v[i];
    }
    __shared__ float rs[256], rs2[256];
    rs[tid] = s; rs2[tid] = s2;
    __syncthreads();
    for (int st = 128; st > 0; st >>= 1) {
        if (tid < st) { rs[tid] += rs[tid + st]; rs2[tid] += rs2[tid + st]; }
        __syncthreads();
    }
    float mu = rs[0] * (1.0f / DD);
    float var = rs2[0] * (1.0f / DD) - mu * mu;
    float rstd = rsqrtf(var + 1e-5f);
#pragma unroll
    for (int i = 0; i < 3; i++) {
        int c = tid + i * 256;
        y[c] = (v[i] - mu) * rstd * g[c] + b[c];
    }
}

// -------------------- tf32 conversion --------------------
__device__ __forceinline__ unsigned int f2tf32(float f) {
    unsigned int r;
    asm("cvt.rna.tf32.f32 %0, %1;" : "=r"(r) : "f"(f));
    return r;
}

// -------------------- TF32 tensor-core GEMM: C[M,N] = A[M,K] @ W[N,K]^T --------------------
// R10 structure (empirically best): register double-buffer prefetch, cvt at smem store,
// TGS=20 padded rows, scalar LDS.32 fragment loads.
// EPI: 0=none, 1=+res, 2=GELU. GUARD: N bounds checks. SWAP: m on blockIdx.x
// (wave covers many m-blocks of the same n -> weight tiles stay resident in L2;
// used for the lm_head whose 154MB weight exceeds L2; measured ~-0.28ms).
#define TGS 20   // smem row stride (16 + 4 pad) -> conflict-free fragment LDS
template <int EPI, bool GUARD, bool SWAP>
__global__ __launch_bounds__(256, 2) void tgemm_kernel(const float* __restrict__ A,
                                                       const float* __restrict__ W,
                                                       const float* __restrict__ res,
                                                       float* __restrict__ C,
                                                       int M, int N, int K) {
    __shared__ unsigned int As[2][128 * TGS];
    __shared__ unsigned int Bs[2][128 * TGS];

    const int tid  = threadIdx.x;
    const int bm   = (SWAP ? blockIdx.x : blockIdx.y) * 128;
    const int bn   = (SWAP ? blockIdx.y : blockIdx.x) * 128;
    const int warp = tid >> 5;
    const int lane = tid & 31;
    const int wm   = (warp >> 1) * 32;   // 4 warps along m
    const int wn   = (warp & 1) * 64;    // 2 warps along n
    const int g    = lane >> 2;          // groupID
    const int tg   = lane & 3;           // thread in group

    float acc[2][8][4];
#pragma unroll
    for (int mi = 0; mi < 2; mi++)
#pragma unroll
        for (int ni = 0; ni < 8; ni++)
#pragma unroll
            for (int r = 0; r < 4; r++) acc[mi][ni][r] = 0.f;

    const int r0 = (tid + 0)   >> 2, kq0 = (tid + 0)   & 3;
    const int r1 = (tid + 256) >> 2, kq1 = (tid + 256) & 3;
    bool bv0 = true, bv1 = true;
    int bn0 = bn + r0, bn1 = bn + r1;
    if (GUARD) {
        bv0 = bn0 < N; if (!bv0) bn0 = N - 1;
        bv1 = bn1 < N; if (!bv1) bn1 = N - 1;
    }
    const float* Ar0 = A + (size_t)(bm + r0) * K + kq0 * 4;
    const float* Ar1 = A + (size_t)(bm + r1) * K + kq1 * 4;
    const float* Wr0 = W + (size_t)bn0 * K + kq0 * 4;
    const float* Wr1 = W + (size_t)bn1 * K + kq1 * 4;

    const int nk = K >> 4;
    float4 pa0, pa1, pb0, pb1;

    // prefetch tile 0
    pa0 = *(const float4*)(Ar0);
    pa1 = *(const float4*)(Ar1);
    pb0 = *(const float4*)(Wr0);
    pb1 = *(const float4*)(Wr1);
    if (GUARD) {
        if (!bv0) pb0 = make_float4(0.f, 0.f, 0.f, 0.f);
        if (!bv1) pb1 = make_float4(0.f, 0.f, 0.f, 0.f);
    }
    // store tile 0 into buffer 0 (cvt at store)
    {
        unsigned int* a = &As[0][r0 * TGS + kq0 * 4];
        a[0] = f2tf32(pa0.x); a[1] = f2tf32(pa0.y); a[2] = f2tf32(pa0.z); a[3] = f2tf32(pa0.w);
        a = &As[0][r1 * TGS + kq1 * 4];
        a[0] = f2tf32(pa1.x); a[1] = f2tf32(pa1.y); a[2] = f2tf32(pa1.z); a[3] = f2tf32(pa1.w);
        unsigned int* b = &Bs[0][r0 * TGS + kq0 * 4];
        b[0] = f2tf32(pb0.x); b[1] = f2tf32(pb0.y); b[2] = f2tf32(pb0.z); b[3] = f2tf32(pb0.w);
        b = &Bs[0][r1 * TGS + kq1 * 4];
        b[0] = f2tf32(pb1.x); b[1] = f2tf32(pb1.y); b[2] = f2tf32(pb1.z); b[3] = f2tf32(pb1.w);
    }
    __syncthreads();

    for (int it = 0; it < nk; it++) {
        const int buf = it & 1;
        if (it + 1 < nk) {
            int k0 = (it + 1) << 4;
            pa0 = *(const float4*)(Ar0 + k0);
            pa1 = *(const float4*)(Ar1 + k0);
            pb0 = *(const float4*)(Wr0 + k0);
            pb1 = *(const float4*)(Wr1 + k0);
            if (GUARD) {
                if (!bv0) pb0 = make_float4(0.f, 0.f, 0.f, 0.f);
                if (!bv1) pb1 = make_float4(0.f, 0.f, 0.f, 0.f);
            }
        }
#pragma unroll
        for (int ka = 0; ka < 16; ka += 8) {
            unsigned int afr[2][4];
#pragma unroll
            for (int mi = 0; mi < 2; mi++) {
                const unsigned int* ab = &As[buf][(wm + mi * 16 + g) * TGS + ka + tg];
                afr[mi][0] = ab[0];
                afr[mi][1] = ab[8 * TGS];
                afr[mi][2] = ab[4];
                afr[mi][3] = ab[8 * TGS + 4];
            }
            unsigned int bfr[8][2];
#pragma unroll
            for (int ni = 0; ni < 8; ni++) {
                const unsigned int* bb = &Bs[buf][(wn + ni * 8 + g) * TGS + ka + tg];
                bfr[ni][0] = bb[0];
                bfr[ni][1] = bb[4];
            }
#pragma unroll
            for (int mi = 0; mi < 2; mi++)
#pragma unroll
                for (int ni = 0; ni < 8; ni++) {
                    float* c = acc[mi][ni];
                    asm volatile(
                        "mma.sync.aligned.m16n8k8.row.col.f32.tf32.tf32.f32 "
                        "{%0,%1,%2,%3}, {%4,%5,%6,%7}, {%8,%9}, {%0,%1,%2,%3};"
                        : "+f"(c[0]), "+f"(c[1]), "+f"(c[2]), "+f"(c[3])
                        : "r"(afr[mi][0]), "r"(afr[mi][1]), "r"(afr[mi][2]), "r"(afr[mi][3]),
                          "r"(bfr[ni][0]), "r"(bfr[ni][1]));
                }
        }
        if (it + 1 < nk) {
            const int nb = buf ^ 1;
            unsigned int* a = &As[nb][r0 * TGS + kq0 * 4];
            a[0] = f2tf32(pa0.x); a[1] = f2tf32(pa0.y); a[2] = f2tf32(pa0.z); a[3] = f2tf32(pa0.w);
            a = &As[nb][r1 * TGS + kq1 * 4];
            a[0] = f2tf32(pa1.x); a[1] = f2tf32(pa1.y); a[2] = f2tf32(pa1.z); a[3] = f2tf32(pa1.w);
            unsigned int* b = &Bs[nb][r0 * TGS + kq0 * 4];
            b[0] = f2tf32(pb0.x); b[1] = f2tf32(pb0.y); b[2] = f2tf32(pb0.z); b[3] = f2tf32(pb0.w);
            b = &Bs[nb][r1 * TGS + kq1 * 4];
            b[0] = f2tf32(pb1.x); b[1] = f2tf32(pb1.y); b[2] = f2tf32(pb1.z); b[3] = f2tf32(pb1.w);
            __syncthreads();
        }
    }

    // epilogue
#pragma unroll
    for (int mi = 0; mi < 2; mi++) {
        int row0 = bm + wm + mi * 16 + g;
#pragma unroll
        for (int ni = 0; ni < 8; ni++) {
            int col0 = bn + wn + ni * 8 + tg * 2;
#pragma unroll
            for (int rr = 0; rr < 2; rr++) {
                int m = row0 + rr * 8;
#pragma unroll
                for (int cc = 0; cc < 2; cc++) {
                    int n = col0 + cc;
                    if (!GUARD || n < N) {
                        float v = acc[mi][ni][rr * 2 + cc];
                        if (EPI == 1) v += res[(size_t)m * N + n];
                        if (EPI == 2) v = 0.5f * v * (1.0f + erff(v * 0.70710678118654752f));
                        C[(size_t)m * N + n] = v;
                    }
                }
            }
        }
    }
}

// -------------------- flash attention (fp32, packed f32x2 FMA) --------------------
// block = (bh, q-tile 64). 256 threads (16x16). Thread: 4q x 4k (k rows tx+16j).
// Heavy q-tiles first. Default launch bounds (94 regs, 2 CTAs/SM) is the
// measured optimum; capping regs for 3 CTAs/SM caused spills and regressed.
#define ATS 68
__global__ __launch_bounds__(256) void flash_attn_kernel(const float* __restrict__ qkv,
                                                         float* __restrict__ o) {
    extern __shared__ float sm[];
    float* Qs = sm;
    float* Ks = sm + 64 * ATS;
    float* Vs = sm + 2 * 64 * ATS;
    float* Ps = sm + 3 * 64 * ATS;

    const int bh = blockIdx.x;
    const int qt = (gridDim.y - 1) - blockIdx.y;   // heavy tiles first
    const int b = bh / HH, h = bh % HH;
    const int tid = threadIdx.x;
    const int tx = tid & 15;
    const int ty = tid >> 4;

    const float* base = qkv + (size_t)b * TT * (3 * DD);

    // load Q tile (scaled)
#pragma unroll
    for (int p = 0; p < 4; p++) {
        int id = p * 256 + tid;
        int row = id >> 4, c4 = (id & 15) * 4;
        float4 v = *(const float4*)(base + (size_t)(qt * 64 + row) * (3 * DD) + h * HD + c4);
        float* q = &Qs[row * ATS + c4];
        q[0] = v.x * 0.125f; q[1] = v.y * 0.125f; q[2] = v.z * 0.125f; q[3] = v.w * 0.125f;
    }

    float m_i[4], l_i[4];
    u64t o_pk[4][2];
#pragma unroll
    for (int i = 0; i < 4; i++) {
        m_i[i] = -1e30f; l_i[i] = 0.f;
        o_pk[i][0] = pk2(0.f, 0.f); o_pk[i][1] = pk2(0.f, 0.f);
    }

    for (int kt = 0; kt <= qt; kt++) {
        __syncthreads();
#pragma unroll
        for (int p = 0; p < 4; p++) {
            int id = p * 256 + tid;
            int row = id >> 4, c4 = (id & 15) * 4;
            const float* src = base + (size_t)(kt * 64 + row) * (3 * DD) + h * HD + c4;
            float4 kv = *(const float4*)(src + DD);
            float4 vv = *(const float4*)(src + 2 * DD);
            *(float4*)&Ks[row * ATS + c4] = kv;
            *(float4*)&Vs[row * ATS + c4] = vv;
        }
        __syncthreads();

        // S = Q K^T, packed over d. Thread's k rows: tx + 16j.
        u64t s_pk[4][4];
#pragma unroll
        for (int i = 0; i < 4; i++)
#pragma unroll
            for (int j = 0; j < 4; j++) s_pk[i][j] = pk2(0.f, 0.f);
        for (int d = 0; d < 64; d += 4) {
            float4 qv[4], kv[4];
#pragma unroll
            for (int i = 0; i < 4; i++) qv[i] = *(float4*)&Qs[(ty * 4 + i) * ATS + d];
#pragma unroll
            for (int j = 0; j < 4; j++) kv[j] = *(float4*)&Ks[(tx + 16 * j) * ATS + d];
#pragma unroll
            for (int i = 0; i < 4; i++) {
                u64t q01 = pk2(qv[i].x, qv[i].y);
                u64t q23 = pk2(qv[i].z, qv[i].w);
#pragma unroll
                for (int j = 0; j < 4; j++) {
                    s_pk[i][j] = ffma2(q01, pk2(kv[j].x, kv[j].y), s_pk[i][j]);
                    s_pk[i][j] = ffma2(q23, pk2(kv[j].z, kv[j].w), s_pk[i][j]);
                }
            }
        }
        float s[4][4];
#pragma unroll
        for (int i = 0; i < 4; i++)
#pragma unroll
            for (int j = 0; j < 4; j++) {
                float lo, hi; upk2(s_pk[i][j], lo, hi);
                s[i][j] = lo + hi;
            }

        if (kt == qt) {
#pragma unroll
            for (int i = 0; i < 4; i++)
#pragma unroll
                for (int j = 0; j < 4; j++)
                    if (tx + 16 * j > ty * 4 + i) s[i][j] = -1e30f;
        }

        // online softmax (reduce across 16 tx lanes)
#pragma unroll
        for (int i = 0; i < 4; i++) {
            float mx = fmaxf(fmaxf(s[i][0], s[i][1]), fmaxf(s[i][2], s[i][3]));
#pragma unroll
            for (int off = 1; off < 16; off <<= 1)
                mx = fmaxf(mx, __shfl_xor_sync(0xffffffffu, mx, off));
            float mnew = fmaxf(m_i[i], mx);
            float corr = __expf(m_i[i] - mnew);
            float rs = 0.f;
            float pv[4];
#pragma unroll
            for (int j = 0; j < 4; j++) {
                float p = __expf(s[i][j] - mnew);
                pv[j] = p; rs += p;
            }
#pragma unroll
            for (int off = 1; off < 16; off <<= 1)
                rs += __shfl_xor_sync(0xffffffffu, rs, off);
            l_i[i] = l_i[i] * corr + rs;
            m_i[i] = mnew;
            u64t c2 = pk2(corr, corr);
            o_pk[i][0] = fmul2(o_pk[i][0], c2);
            o_pk[i][1] = fmul2(o_pk[i][1], c2);
#pragma unroll
            for (int j = 0; j < 4; j++)
                Ps[(ty * 4 + i) * ATS + tx + 16 * j] = pv[j];
        }
        __syncthreads();

        // O += P @ V (thread: 4q x 4d, d0 = tx*4), packed over d
        for (int k = 0; k < 64; k += 4) {
            float4 pr[4], vr[4];
#pragma unroll
            for (int i = 0; i < 4; i++) pr[i] = *(float4*)&Ps[(ty * 4 + i) * ATS + k];
#pragma unroll
            for (int j = 0; j < 4; j++) vr[j] = *(float4*)&Vs[(k + j) * ATS + tx * 4];
#pragma unroll
            for (int j = 0; j < 4; j++) {
                u64t v01 = pk2(vr[j].x, vr[j].y);
                u64t v23 = pk2(vr[j].z, vr[j].w);
#pragma unroll
                for (int i = 0; i < 4; i++) {
                    float p = (j == 0) ? pr[i].x : (j == 1) ? pr[i].y : (j == 2) ? pr[i].z : pr[i].w;
                    u64t p2 = pk2(p, p);
                    o_pk[i][0] = ffma2(p2, v01, o_pk[i][0]);
                    o_pk[i][1] = ffma2(p2, v23, o_pk[i][1]);
                }
            }
        }
    }

    // write O
#pragma unroll
    for (int i = 0; i < 4; i++) {
        float inv = 1.0f / l_i[i];
        int t = qt * 64 + ty * 4 + i;
        float* dst = o + ((size_t)b * TT + t) * DD + h * HD + tx * 4;
        float a0, a1, a2, a3;
        upk2(o_pk[i][0], a0, a1);
        upk2(o_pk[i][1], a2, a3);
        dst[0] = a0 * inv; dst[1] = a1 * inv; dst[2] = a2 * inv; dst[3] = a3 * inv;
    }
}

// -------------------- launch --------------------
extern "C" void kernel_launch(void* const* d_in, const int* in_sizes, int n_in,
                              void* d_out, int out_size) {
    const int*   idx   = (const int*)  d_in[0];
    const float* wte   = (const float*)d_in[1];
    const float* wpe   = (const float*)d_in[2];
    const float* ln1_g = (const float*)d_in[3];
    const float* ln1_b = (const float*)d_in[4];
    const float* qkv_w = (const float*)d_in[5];
    const float* out_w = (const float*)d_in[6];
    const float* ln2_g = (const float*)d_in[7];
    const float* ln2_b = (const float*)d_in[8];
    const float* fc1_w = (const float*)d_in[9];
    const float* fc2_w = (const float*)d_in[10];
    const float* lnf_g = (const float*)d_in[11];
    const float* lnf_b = (const float*)d_in[12];
    float* out = (float*)d_out;

    static float *p_x = nullptr, *p_ln = nullptr, *p_qkv = nullptr,
                 *p_o = nullptr, *p_mlp = nullptr;
    static const int ATT_SMEM = 4 * 64 * ATS * (int)sizeof(float);   // 69,632
    if (!p_x) {
        cudaGetSymbolAddress((void**)&p_x,   g_x);
        cudaGetSymbolAddress((void**)&p_ln,  g_ln);
        cudaGetSymbolAddress((void**)&p_qkv, g_qkv);
        cudaGetSymbolAddress((void**)&p_o,   g_o);
        cudaGetSymbolAddress((void**)&p_mlp, g_mlp);
        cudaFuncSetAttribute(flash_attn_kernel,
                             cudaFuncAttributeMaxDynamicSharedMemorySize, ATT_SMEM);
    }

    embed_kernel<<<(BT * DD + 255) / 256, 256>>>(idx, wte, wpe, p_x);

    dim3 grid_qkv(3 * DD / 128, BT / 128);       // (18, 32)
    dim3 grid_d  (DD / 128, BT / 128);           // (6, 32)
    dim3 grid_f  (DF / 128, BT / 128);           // (24, 32)
    dim3 grid_v  (BT / 128, (NV + 127) / 128);   // (32, 393)  m fastest (SWAP)
    dim3 grid_att(BB * HH, TT / 64);             // (48, 16)

    for (int l = 0; l < LL; l++) {
        ln_kernel<<<BT, 256>>>(p_x, ln1_g + l * DD, ln1_b + l * DD, p_ln);
        tgemm_kernel<0, false, false><<<grid_qkv, 256>>>(
            p_ln, qkv_w + (size_t)l * 3 * DD * DD, nullptr, p_qkv, BT, 3 * DD, DD);
        flash_attn_kernel<<<grid_att, 256, ATT_SMEM>>>(p_qkv, p_o);
        tgemm_kernel<1, false, false><<<grid_d, 256>>>(
            p_o, out_w + (size_t)l * DD * DD, p_x, p_x, BT, DD, DD);
        ln_kernel<<<BT, 256>>>(p_x, ln2_g + l * DD, ln2_b + l * DD, p_ln);
        tgemm_kernel<2, false, false><<<grid_f, 256>>>(
            p_ln, fc1_w + (size_t)l * DF * DD, nullptr, p_mlp, BT, DF, DD);
        tgemm_kernel<1, false, false><<<grid_d, 256>>>(
            p_mlp, fc2_w + (size_t)l * DD * DF, p_x, p_x, BT, DD, DF);
    }

    ln_kernel<<<BT, 256>>>(p_x, lnf_g, lnf_b, p_ln);
    tgemm_kernel<0, true, true><<<grid_v, 256>>>(
        p_ln, wte, nullptr, out, BT, NV, DD);
}

// round 17
// speedup vs baseline: 1.5708x; 1.5708x over previous
#include <cuda_runtime.h>
#include <cuda_bf16.h>
#include <math.h>
#include <stdint.h>

// Problem constants
#define BB 4
#define TT 1024
#define LL 12
#define HH 12
#define DD 768
#define HD 64
#define DF 3072
#define BT 4096          // B*T
#define NV 50257

// -------------------- scratch (device globals; no allocations) --------------------
__device__ float g_x  [BT * DD];
__device__ float g_ln [BT * DD];
__device__ float g_qkv[BT * 3 * DD];
__device__ float g_o  [BT * DD];
__device__ float g_mlp[BT * DF];

// -------------------- packed f32x2 helpers (Blackwell FFMA2) --------------------
typedef unsigned long long u64t;
__device__ __forceinline__ u64t pk2(float lo, float hi) {
    u64t r; asm("mov.b64 %0, {%1, %2};" : "=l"(r) : "f"(lo), "f"(hi)); return r;
}
__device__ __forceinline__ void upk2(u64t v, float& lo, float& hi) {
    asm("mov.b64 {%0, %1}, %2;" : "=f"(lo), "=f"(hi) : "l"(v));
}
__device__ __forceinline__ u64t ffma2(u64t a, u64t b, u64t c) {
    u64t d; asm("fma.rn.f32x2 %0, %1, %2, %3;" : "=l"(d) : "l"(a), "l"(b), "l"(c)); return d;
}
__device__ __forceinline__ u64t fmul2(u64t a, u64t b) {
    u64t d; asm("mul.rn.f32x2 %0, %1, %2;" : "=l"(d) : "l"(a), "l"(b)); return d;
}

// -------------------- embedding --------------------
__global__ void embed_kernel(const int* __restrict__ idx,
                             const float* __restrict__ wte,
                             const float* __restrict__ wpe,
                             float* __restrict__ x) {
    int i = blockIdx.x * 256 + threadIdx.x;
    if (i >= BT * DD) return;
    int bt = i / DD, d = i - bt * DD;
    int t = bt & (TT - 1);
    x[i] = wte[(size_t)idx[bt] * DD + d] + wpe[t * DD + d];
}

// -------------------- layernorm --------------------
__global__ __launch_bounds__(256) void ln_kernel(const float* __restrict__ in,
                                                 const float* __restrict__ g,
                                                 const float* __restrict__ b,
                                                 float* __restrict__ out) {
    int row = blockIdx.x;
    const float* x = in + (size_t)row * DD;
    float* y = out + (size_t)row * DD;
    int tid = threadIdx.x;
    float v[3];
    float s = 0.f, s2 = 0.f;
#pragma unroll
    for (int i = 0; i < 3; i++) {
        v[i] = x[tid + i * 256];
        s += v[i]; s2 += v[i] * v[i];
    }
    __shared__ float rs[256], rs2[256];
    rs[tid] = s; rs2[tid] = s2;
    __syncthreads();
    for (int st = 128; st > 0; st >>= 1) {
        if (tid < st) { rs[tid] += rs[tid + st]; rs2[tid] += rs2[tid + st]; }
        __syncthreads();
    }
    float mu = rs[0] * (1.0f / DD);
    float var = rs2[0] * (1.0f / DD) - mu * mu;
    float rstd = rsqrtf(var + 1e-5f);
#pragma unroll
    for (int i = 0; i < 3; i++) {
        int c = tid + i * 256;
        y[c] = (v[i] - mu) * rstd * g[c] + b[c];
    }
}

// -------------------- tf32 conversion --------------------
__device__ __forceinline__ unsigned int f2tf32(float f) {
    unsigned int r;
    asm("cvt.rna.tf32.f32 %0, %1;" : "=r"(r) : "f"(f));
    return r;
}

// -------------------- TF32 tensor-core GEMM: C[M,N] = A[M,K] @ W[N,K]^T --------------------
// R10 structure (empirically best mma.sync config): register double-buffer prefetch,
// cvt at smem store, TGS=20 padded rows, scalar LDS.32 fragment loads.
// NOTE: tcgen05 path is blocked by the harness toolchain (PTX target compute_103,
// no 'a' features) — mma.sync is the tensor ceiling here.
// EPI: 0=none, 1=+res, 2=GELU. GUARD: N bounds checks. SWAP: m on blockIdx.x
// (wave covers many m-blocks of the same n -> lm_head weight tiles stay in L2).
#define TGS 20   // smem row stride (16 + 4 pad) -> conflict-free fragment LDS
template <int EPI, bool GUARD, bool SWAP>
__global__ __launch_bounds__(256, 2) void tgemm_kernel(const float* __restrict__ A,
                                                       const float* __restrict__ W,
                                                       const float* __restrict__ res,
                                                       float* __restrict__ C,
                                                       int M, int N, int K) {
    __shared__ unsigned int As[2][128 * TGS];
    __shared__ unsigned int Bs[2][128 * TGS];

    const int tid  = threadIdx.x;
    const int bm   = (SWAP ? blockIdx.x : blockIdx.y) * 128;
    const int bn   = (SWAP ? blockIdx.y : blockIdx.x) * 128;
    const int warp = tid >> 5;
    const int lane = tid & 31;
    const int wm   = (warp >> 1) * 32;   // 4 warps along m
    const int wn   = (warp & 1) * 64;    // 2 warps along n
    const int g    = lane >> 2;          // groupID
    const int tg   = lane & 3;           // thread in group

    float acc[2][8][4];
#pragma unroll
    for (int mi = 0; mi < 2; mi++)
#pragma unroll
        for (int ni = 0; ni < 8; ni++)
#pragma unroll
            for (int r = 0; r < 4; r++) acc[mi][ni][r] = 0.f;

    const int r0 = (tid + 0)   >> 2, kq0 = (tid + 0)   & 3;
    const int r1 = (tid + 256) >> 2, kq1 = (tid + 256) & 3;
    bool bv0 = true, bv1 = true;
    int bn0 = bn + r0, bn1 = bn + r1;
    if (GUARD) {
        bv0 = bn0 < N; if (!bv0) bn0 = N - 1;
        bv1 = bn1 < N; if (!bv1) bn1 = N - 1;
    }
    const float* Ar0 = A + (size_t)(bm + r0) * K + kq0 * 4;
    const float* Ar1 = A + (size_t)(bm + r1) * K + kq1 * 4;
    const float* Wr0 = W + (size_t)bn0 * K + kq0 * 4;
    const float* Wr1 = W + (size_t)bn1 * K + kq1 * 4;

    const int nk = K >> 4;
    float4 pa0, pa1, pb0, pb1;

    // prefetch tile 0
    pa0 = *(const float4*)(Ar0);
    pa1 = *(const float4*)(Ar1);
    pb0 = *(const float4*)(Wr0);
    pb1 = *(const float4*)(Wr1);
    if (GUARD) {
        if (!bv0) pb0 = make_float4(0.f, 0.f, 0.f, 0.f);
        if (!bv1) pb1 = make_float4(0.f, 0.f, 0.f, 0.f);
    }
    // store tile 0 into buffer 0 (cvt at store)
    {
        unsigned int* a = &As[0][r0 * TGS + kq0 * 4];
        a[0] = f2tf32(pa0.x); a[1] = f2tf32(pa0.y); a[2] = f2tf32(pa0.z); a[3] = f2tf32(pa0.w);
        a = &As[0][r1 * TGS + kq1 * 4];
        a[0] = f2tf32(pa1.x); a[1] = f2tf32(pa1.y); a[2] = f2tf32(pa1.z); a[3] = f2tf32(pa1.w);
        unsigned int* b = &Bs[0][r0 * TGS + kq0 * 4];
        b[0] = f2tf32(pb0.x); b[1] = f2tf32(pb0.y); b[2] = f2tf32(pb0.z); b[3] = f2tf32(pb0.w);
        b = &Bs[0][r1 * TGS + kq1 * 4];
        b[0] = f2tf32(pb1.x); b[1] = f2tf32(pb1.y); b[2] = f2tf32(pb1.z); b[3] = f2tf32(pb1.w);
    }
    __syncthreads();

    for (int it = 0; it < nk; it++) {
        const int buf = it & 1;
        if (it + 1 < nk) {
            int k0 = (it + 1) << 4;
            pa0 = *(const float4*)(Ar0 + k0);
            pa1 = *(const float4*)(Ar1 + k0);
            pb0 = *(const float4*)(Wr0 + k0);
            pb1 = *(const float4*)(Wr1 + k0);
            if (GUARD) {
                if (!bv0) pb0 = make_float4(0.f, 0.f, 0.f, 0.f);
                if (!bv1) pb1 = make_float4(0.f, 0.f, 0.f, 0.f);
            }
        }
#pragma unroll
        for (int ka = 0; ka < 16; ka += 8) {
            unsigned int afr[2][4];
#pragma unroll
            for (int mi = 0; mi < 2; mi++) {
                const unsigned int* ab = &As[buf][(wm + mi * 16 + g) * TGS + ka + tg];
                afr[mi][0] = ab[0];
                afr[mi][1] = ab[8 * TGS];
                afr[mi][2] = ab[4];
                afr[mi][3] = ab[8 * TGS + 4];
            }
            unsigned int bfr[8][2];
#pragma unroll
            for (int ni = 0; ni < 8; ni++) {
                const unsigned int* bb = &Bs[buf][(wn + ni * 8 + g) * TGS + ka + tg];
                bfr[ni][0] = bb[0];
                bfr[ni][1] = bb[4];
            }
#pragma unroll
            for (int mi = 0; mi < 2; mi++)
#pragma unroll
                for (int ni = 0; ni < 8; ni++) {
                    float* c = acc[mi][ni];
                    asm volatile(
                        "mma.sync.aligned.m16n8k8.row.col.f32.tf32.tf32.f32 "
                        "{%0,%1,%2,%3}, {%4,%5,%6,%7}, {%8,%9}, {%0,%1,%2,%3};"
                        : "+f"(c[0]), "+f"(c[1]), "+f"(c[2]), "+f"(c[3])
                        : "r"(afr[mi][0]), "r"(afr[mi][1]), "r"(afr[mi][2]), "r"(afr[mi][3]),
                          "r"(bfr[ni][0]), "r"(bfr[ni][1]));
                }
        }
        if (it + 1 < nk) {
            const int nb = buf ^ 1;
            unsigned int* a = &As[nb][r0 * TGS + kq0 * 4];
            a[0] = f2tf32(pa0.x); a[1] = f2tf32(pa0.y); a[2] = f2tf32(pa0.z); a[3] = f2tf32(pa0.w);
            a = &As[nb][r1 * TGS + kq1 * 4];
            a[0] = f2tf32(pa1.x); a[1] = f2tf32(pa1.y); a[2] = f2tf32(pa1.z); a[3] = f2tf32(pa1.w);
            unsigned int* b = &Bs[nb][r0 * TGS + kq0 * 4];
            b[0] = f2tf32(pb0.x); b[1] = f2tf32(pb0.y); b[2] = f2tf32(pb0.z); b[3] = f2tf32(pb0.w);
            b = &Bs[nb][r1 * TGS + kq1 * 4];
            b[0] = f2tf32(pb1.x); b[1] = f2tf32(pb1.y); b[2] = f2tf32(pb1.z); b[3] = f2tf32(pb1.w);
            __syncthreads();
        }
    }

    // epilogue
#pragma unroll
    for (int mi = 0; mi < 2; mi++) {
        int row0 = bm + wm + mi * 16 + g;
#pragma unroll
        for (int ni = 0; ni < 8; ni++) {
            int col0 = bn + wn + ni * 8 + tg * 2;
#pragma unroll
            for (int rr = 0; rr < 2; rr++) {
                int m = row0 + rr * 8;
#pragma unroll
                for (int cc = 0; cc < 2; cc++) {
                    int n = col0 + cc;
                    if (!GUARD || n < N) {
                        float v = acc[mi][ni][rr * 2 + cc];
                        if (EPI == 1) v += res[(size_t)m * N + n];
                        if (EPI == 2) v = 0.5f * v * (1.0f + erff(v * 0.70710678118654752f));
                        C[(size_t)m * N + n] = v;
                    }
                }
            }
        }
    }
}

// -------------------- flash attention (fp32, packed f32x2 FMA) --------------------
// block = (bh, q-tile 64). 256 threads (16x16). Thread: 4q x 4k (k rows tx+16j).
// Heavy q-tiles first. Default launch bounds (94 regs, 2 CTAs/SM) measured optimum;
// capping regs for 3 CTAs/SM caused spills and regressed.
#define ATS 68
__global__ __launch_bounds__(256) void flash_attn_kernel(const float* __restrict__ qkv,
                                                         float* __restrict__ o) {
    extern __shared__ float sm[];
    float* Qs = sm;
    float* Ks = sm + 64 * ATS;
    float* Vs = sm + 2 * 64 * ATS;
    float* Ps = sm + 3 * 64 * ATS;

    const int bh = blockIdx.x;
    const int qt = (gridDim.y - 1) - blockIdx.y;   // heavy tiles first
    const int b = bh / HH, h = bh % HH;
    const int tid = threadIdx.x;
    const int tx = tid & 15;
    const int ty = tid >> 4;

    const float* base = qkv + (size_t)b * TT * (3 * DD);

    // load Q tile (scaled)
#pragma unroll
    for (int p = 0; p < 4; p++) {
        int id = p * 256 + tid;
        int row = id >> 4, c4 = (id & 15) * 4;
        float4 v = *(const float4*)(base + (size_t)(qt * 64 + row) * (3 * DD) + h * HD + c4);
        float* q = &Qs[row * ATS + c4];
        q[0] = v.x * 0.125f; q[1] = v.y * 0.125f; q[2] = v.z * 0.125f; q[3] = v.w * 0.125f;
    }

    float m_i[4], l_i[4];
    u64t o_pk[4][2];
#pragma unroll
    for (int i = 0; i < 4; i++) {
        m_i[i] = -1e30f; l_i[i] = 0.f;
        o_pk[i][0] = pk2(0.f, 0.f); o_pk[i][1] = pk2(0.f, 0.f);
    }

    for (int kt = 0; kt <= qt; kt++) {
        __syncthreads();
#pragma unroll
        for (int p = 0; p < 4; p++) {
            int id = p * 256 + tid;
            int row = id >> 4, c4 = (id & 15) * 4;
            const float* src = base + (size_t)(kt * 64 + row) * (3 * DD) + h * HD + c4;
            float4 kv = *(const float4*)(src + DD);
            float4 vv = *(const float4*)(src + 2 * DD);
            *(float4*)&Ks[row * ATS + c4] = kv;
            *(float4*)&Vs[row * ATS + c4] = vv;
        }
        __syncthreads();

        // S = Q K^T, packed over d. Thread's k rows: tx + 16j.
        u64t s_pk[4][4];
#pragma unroll
        for (int i = 0; i < 4; i++)
#pragma unroll
            for (int j = 0; j < 4; j++) s_pk[i][j] = pk2(0.f, 0.f);
        for (int d = 0; d < 64; d += 4) {
            float4 qv[4], kv[4];
#pragma unroll
            for (int i = 0; i < 4; i++) qv[i] = *(float4*)&Qs[(ty * 4 + i) * ATS + d];
#pragma unroll
            for (int j = 0; j < 4; j++) kv[j] = *(float4*)&Ks[(tx + 16 * j) * ATS + d];
#pragma unroll
            for (int i = 0; i < 4; i++) {
                u64t q01 = pk2(qv[i].x, qv[i].y);
                u64t q23 = pk2(qv[i].z, qv[i].w);
#pragma unroll
                for (int j = 0; j < 4; j++) {
                    s_pk[i][j] = ffma2(q01, pk2(kv[j].x, kv[j].y), s_pk[i][j]);
                    s_pk[i][j] = ffma2(q23, pk2(kv[j].z, kv[j].w), s_pk[i][j]);
                }
            }
        }
        float s[4][4];
#pragma unroll
        for (int i = 0; i < 4; i++)
#pragma unroll
            for (int j = 0; j < 4; j++) {
                float lo, hi; upk2(s_pk[i][j], lo, hi);
                s[i][j] = lo + hi;
            }

        if (kt == qt) {
#pragma unroll
            for (int i = 0; i < 4; i++)
#pragma unroll
                for (int j = 0; j < 4; j++)
                    if (tx + 16 * j > ty * 4 + i) s[i][j] = -1e30f;
        }

        // online softmax (reduce across 16 tx lanes)
#pragma unroll
        for (int i = 0; i < 4; i++) {
            float mx = fmaxf(fmaxf(s[i][0], s[i][1]), fmaxf(s[i][2], s[i][3]));
#pragma unroll
            for (int off = 1; off < 16; off <<= 1)
                mx = fmaxf(mx, __shfl_xor_sync(0xffffffffu, mx, off));
            float mnew = fmaxf(m_i[i], mx);
            float corr = __expf(m_i[i] - mnew);
            float rs = 0.f;
            float pv[4];
#pragma unroll
            for (int j = 0; j < 4; j++) {
                float p = __expf(s[i][j] - mnew);
                pv[j] = p; rs += p;
            }
#pragma unroll
            for (int off = 1; off < 16; off <<= 1)
                rs += __shfl_xor_sync(0xffffffffu, rs, off);
            l_i[i] = l_i[i] * corr + rs;
            m_i[i] = mnew;
            u64t c2 = pk2(corr, corr);
            o_pk[i][0] = fmul2(o_pk[i][0], c2);
            o_pk[i][1] = fmul2(o_pk[i][1], c2);
#pragma unroll
            for (int j = 0; j < 4; j++)
                Ps[(ty * 4 + i) * ATS + tx + 16 * j] = pv[j];
        }
        __syncthreads();

        // O += P @ V (thread: 4q x 4d, d0 = tx*4), packed over d
        for (int k = 0; k < 64; k += 4) {
            float4 pr[4], vr[4];
#pragma unroll
            for (int i = 0; i < 4; i++) pr[i] = *(float4*)&Ps[(ty * 4 + i) * ATS + k];
#pragma unroll
            for (int j = 0; j < 4; j++) vr[j] = *(float4*)&Vs[(k + j) * ATS + tx * 4];
#pragma unroll
            for (int j = 0; j < 4; j++) {
                u64t v01 = pk2(vr[j].x, vr[j].y);
                u64t v23 = pk2(vr[j].z, vr[j].w);
#pragma unroll
                for (int i = 0; i < 4; i++) {
                    float p = (j == 0) ? pr[i].x : (j == 1) ? pr[i].y : (j == 2) ? pr[i].z : pr[i].w;
                    u64t p2 = pk2(p, p);
                    o_pk[i][0] = ffma2(p2, v01, o_pk[i][0]);
                    o_pk[i][1] = ffma2(p2, v23, o_pk[i][1]);
                }
            }
        }
    }

    // write O
#pragma unroll
    for (int i = 0; i < 4; i++) {
        float inv = 1.0f / l_i[i];
        int t = qt * 64 + ty * 4 + i;
        float* dst = o + ((size_t)b * TT + t) * DD + h * HD + tx * 4;
        float a0, a1, a2, a3;
        upk2(o_pk[i][0], a0, a1);
        upk2(o_pk[i][1], a2, a3);
        dst[0] = a0 * inv; dst[1] = a1 * inv; dst[2] = a2 * inv; dst[3] = a3 * inv;
    }
}

// -------------------- launch --------------------
extern "C" void kernel_launch(void* const* d_in, const int* in_sizes, int n_in,
                              void* d_out, int out_size) {
    const int*   idx   = (const int*)  d_in[0];
    const float* wte   = (const float*)d_in[1];
    const float* wpe   = (const float*)d_in[2];
    const float* ln1_g = (const float*)d_in[3];
    const float* ln1_b = (const float*)d_in[4];
    const float* qkv_w = (const float*)d_in[5];
    const float* out_w = (const float*)d_in[6];
    const float* ln2_g = (const float*)d_in[7];
    const float* ln2_b = (const float*)d_in[8];
    const float* fc1_w = (const float*)d_in[9];
    const float* fc2_w = (const float*)d_in[10];
    const float* lnf_g = (const float*)d_in[11];
    const float* lnf_b = (const float*)d_in[12];
    float* out = (float*)d_out;

    static float *p_x = nullptr, *p_ln = nullptr, *p_qkv = nullptr,
                 *p_o = nullptr, *p_mlp = nullptr;
    static const int ATT_SMEM = 4 * 64 * ATS * (int)sizeof(float);   // 69,632
    if (!p_x) {
        cudaGetSymbolAddress((void**)&p_x,   g_x);
        cudaGetSymbolAddress((void**)&p_ln,  g_ln);
        cudaGetSymbolAddress((void**)&p_qkv, g_qkv);
        cudaGetSymbolAddress((void**)&p_o,   g_o);
        cudaGetSymbolAddress((void**)&p_mlp, g_mlp);
        cudaFuncSetAttribute(flash_attn_kernel,
                             cudaFuncAttributeMaxDynamicSharedMemorySize, ATT_SMEM);
    }

    embed_kernel<<<(BT * DD + 255) / 256, 256>>>(idx, wte, wpe, p_x);

    dim3 grid_qkv(3 * DD / 128, BT / 128);       // (18, 32)
    dim3 grid_d  (DD / 128, BT / 128);           // (6, 32)
    dim3 grid_f  (DF / 128, BT / 128);           // (24, 32)
    dim3 grid_v  (BT / 128, (NV + 127) / 128);   // (32, 393)  m fastest (SWAP)
    dim3 grid_att(BB * HH, TT / 64);             // (48, 16)

    for (int l = 0; l < LL; l++) {
        ln_kernel<<<BT, 256>>>(p_x, ln1_g + l * DD, ln1_b + l * DD, p_ln);
        tgemm_kernel<0, false, false><<<grid_qkv, 256>>>(
            p_ln, qkv_w + (size_t)l * 3 * DD * DD, nullptr, p_qkv, BT, 3 * DD, DD);
        flash_attn_kernel<<<grid_att, 256, ATT_SMEM>>>(p_qkv, p_o);
        tgemm_kernel<1, false, false><<<grid_d, 256>>>(
            p_o, out_w + (size_t)l * DD * DD, p_x, p_x, BT, DD, DD);
        ln_kernel<<<BT, 256>>>(p_x, ln2_g + l * DD, ln2_b + l * DD, p_ln);
        tgemm_kernel<2, false, false><<<grid_f, 256>>>(
            p_ln, fc1_w + (size_t)l * DF * DD, nullptr, p_mlp, BT, DF, DD);
        tgemm_kernel<1, false, false><<<grid_d, 256>>>(
            p_mlp, fc2_w + (size_t)l * DD * DF, p_x, p_x, BT, DD, DF);
    }

    ln_kernel<<<BT, 256>>>(p_x, lnf_g, lnf_b, p_ln);
    tgemm_kernel<0, true, true><<<grid_v, 256>>>(
        p_ln, wte, nullptr, out, BT, NV, DD);
}